// round 6
// baseline (speedup 1.0000x reference)
#include <cuda_runtime.h>

#define WARPS_PER_BLOCK 4
#define THREADS 128
#define GRID_BLOCKS 512
#define MAX_BLOCKS 512

__device__ __align__(16) float g_w2[64];
__device__ float g_partials[MAX_BLOCKS * 3];
__device__ unsigned int g_count = 0;

__device__ __forceinline__ float wsum(float v) {
#pragma unroll
    for (int o = 16; o > 0; o >>= 1) v += __shfl_xor_sync(0xffffffffu, v, o);
    return v;
}

// -log(sigmoid(x)) = softplus(-x); fast + stable (tol is 1e-3)
__device__ __forceinline__ float nlsig(float x) {
    float z = -x;
    return fmaxf(z, 0.f) + __logf(1.f + __expf(-fabsf(z)));
}

// w2[d] = sum_e att_w_W[d,e] * att_v_W[64+e]
__global__ void precompute_w2(const float* __restrict__ W, const float* __restrict__ vW) {
    const int d = threadIdx.x;
    const float4* Wr = (const float4*)(W + d * 64);
    const float4* vr = (const float4*)(vW + 64);
    float s = 0.f;
#pragma unroll
    for (int e = 0; e < 16; e++) {
        float4 w = __ldg(Wr + e);
        float4 v = __ldg(vr + e);
        s += w.x * v.x + w.y * v.y + w.z * v.z + w.w * v.w;
    }
    g_w2[d] = s;
}

struct Ids { int aid, pid, nid, uid, nrid, prid, nrel; };

struct Emb {
    float2 u, ar, a, p, n, nri;
    float2 am[4], pm[4], nm[4];
    float biasP, biasN, biasNR;
};

__device__ __forceinline__ Ids load_ids(
    const int* __restrict__ u_id, const int* __restrict__ anchor_i_id,
    const int* __restrict__ pos_r_id, const int* __restrict__ pos_i_id,
    const int* __restrict__ neg_r_id, const int* __restrict__ neg_i_id,
    const int* __restrict__ neg_ri_id, int b)
{
    Ids s;
    s.aid  = __ldg(anchor_i_id + b);
    s.pid  = __ldg(pos_i_id + b);
    s.nid  = __ldg(neg_i_id + b);
    s.uid  = __ldg(u_id + b);
    s.nrid = __ldg(neg_ri_id + b);
    s.prid = __ldg(pos_r_id + b);
    s.nrel = __ldg(neg_r_id + b);
    return s;
}

__device__ __forceinline__ Emb load_emb(
    const Ids& id, int4 ma, int4 mp, int4 mn, int lane,
    const float* __restrict__ user_emb, const float* __restrict__ item_emb,
    const float* __restrict__ item_emb_r, const float* __restrict__ item_bias,
    const float* __restrict__ meta_emb)
{
    Emb e;
    e.u   = __ldg((const float2*)user_emb   + (size_t)id.uid  * 32 + lane);
    e.ar  = __ldg((const float2*)item_emb_r + (size_t)id.aid  * 32 + lane);
    e.a   = __ldg((const float2*)item_emb   + (size_t)id.aid  * 32 + lane);
    e.p   = __ldg((const float2*)item_emb   + (size_t)id.pid  * 32 + lane);
    e.n   = __ldg((const float2*)item_emb   + (size_t)id.nid  * 32 + lane);
    e.nri = __ldg((const float2*)item_emb   + (size_t)id.nrid * 32 + lane);
    const int mai[4] = {ma.x, ma.y, ma.z, ma.w};
    const int mpi[4] = {mp.x, mp.y, mp.z, mp.w};
    const int mni[4] = {mn.x, mn.y, mn.z, mn.w};
#pragma unroll
    for (int g = 0; g < 4; g++) {
        e.am[g] = __ldg((const float2*)meta_emb + (size_t)mai[g] * 32 + lane);
        e.pm[g] = __ldg((const float2*)meta_emb + (size_t)mpi[g] * 32 + lane);
        e.nm[g] = __ldg((const float2*)meta_emb + (size_t)mni[g] * 32 + lane);
    }
    e.biasP  = __ldg(item_bias + id.pid);
    e.biasN  = __ldg(item_bias + id.nid);
    e.biasNR = __ldg(item_bias + id.nrid);
    return e;
}

__global__ void __launch_bounds__(THREADS) actr_main(
    const int* __restrict__ u_id, const int* __restrict__ anchor_i_id,
    const int* __restrict__ pos_r_id, const int* __restrict__ pos_i_id,
    const int* __restrict__ neg_r_id, const int* __restrict__ neg_i_id,
    const int* __restrict__ neg_ri_id, const int* __restrict__ item_meta,
    const float* __restrict__ user_emb, const float* __restrict__ rel_emb,
    const float* __restrict__ item_emb, const float* __restrict__ item_emb_r,
    const float* __restrict__ item_bias, const float* __restrict__ rel_bias,
    const float* __restrict__ meta_emb,
    float* __restrict__ out, int B, float invB)
{
    const int lane = threadIdx.x & 31;
    const int wid = threadIdx.x >> 5;
    const int S = gridDim.x * WARPS_PER_BLOCK;   // total warps = sample stride

    // ---- loop-invariant, warp-uniform data (hoisted)
    float2 w2 = __ldg((const float2*)g_w2 + lane);
    float2 re[3];
    float relb[3];
#pragma unroll
    for (int r = 0; r < 3; r++) {
        re[r] = __ldg((const float2*)rel_emb + r * 32 + lane);
        relb[r] = __ldg(rel_bias + r);
    }

    float accSeq = 0.f, accRel = 0.f, accItm = 0.f;

    const int b0 = blockIdx.x * WARPS_PER_BLOCK + wid;
    const int Bm1 = B - 1;

    // ---- 3-stage pipeline prologue (clamped loads are harmless; accumulation gated)
    Ids idC = load_ids(u_id, anchor_i_id, pos_r_id, pos_i_id, neg_r_id, neg_i_id, neg_ri_id,
                       min(b0, Bm1));
    int4 maC = __ldg((const int4*)item_meta + idC.aid);
    int4 mpC = __ldg((const int4*)item_meta + idC.pid);
    int4 mnC = __ldg((const int4*)item_meta + idC.nid);
    Ids idN = load_ids(u_id, anchor_i_id, pos_r_id, pos_i_id, neg_r_id, neg_i_id, neg_ri_id,
                       min(b0 + S, Bm1));
    int4 maN = __ldg((const int4*)item_meta + idN.aid);
    int4 mpN = __ldg((const int4*)item_meta + idN.pid);
    int4 mnN = __ldg((const int4*)item_meta + idN.nid);
    Emb eC = load_emb(idC, maC, mpC, mnC, lane, user_emb, item_emb, item_emb_r, item_bias, meta_emb);

    for (int b = b0; b < B; b += S) {
        // ---- stage A: ids for sample b+2S (arrive by late this iteration)
        Ids idNN = load_ids(u_id, anchor_i_id, pos_r_id, pos_i_id, neg_r_id, neg_i_id, neg_ri_id,
                            min(b + 2 * S, Bm1));

        // ================= compute phase 1 (uses eC, fully resident) =================
        // relation prediction: softmax_r( rel_bias[r] - ||u + a_r - rel_emb[r]||^2 )
        float rw[3];
#pragma unroll
        for (int r = 0; r < 3; r++) {
            float dx = eC.u.x + eC.ar.x - re[r].x;
            float dy = eC.u.y + eC.ar.y - re[r].y;
            rw[r] = relb[r] - wsum(dx * dx + dy * dy);
        }
        float mx = fmaxf(rw[0], fmaxf(rw[1], rw[2]));
        float ssum = 0.f;
#pragma unroll
        for (int r = 0; r < 3; r++) { rw[r] = __expf(rw[r] - mx); ssum += rw[r]; }
        float inv = __frcp_rn(ssum);
#pragma unroll
        for (int r = 0; r < 3; r++) rw[r] *= inv;

        // attention coef: softmax_c( i_plus[c] . w2 )
        float cf[5];
        cf[0] = wsum(eC.a.x * w2.x + eC.a.y * w2.y);
#pragma unroll
        for (int g = 0; g < 4; g++)
            cf[1 + g] = wsum(eC.am[g].x * w2.x + eC.am[g].y * w2.y);
        mx = cf[0];
#pragma unroll
        for (int c = 1; c < 5; c++) mx = fmaxf(mx, cf[c]);
        ssum = 0.f;
#pragma unroll
        for (int c = 0; c < 5; c++) { cf[c] = __expf(cf[c] - mx); ssum += cf[c]; }
        inv = __frcp_rn(ssum);
#pragma unroll
        for (int c = 0; c < 5; c++) cf[c] *= inv;

        // ---- stage B: embedding gathers for sample b+S (meta indices resolved last iter).
        // Issued here so they have the whole phase-2 compute shadow before first use.
        Emb eN = load_emb(idN, maN, mpN, mnN, lane, user_emb, item_emb, item_emb_r, item_bias, meta_emb);

        // ---- stage A cont.: meta indices for b+2S (idNN has arrived by now)
        int4 maNN = __ldg((const int4*)item_meta + idNN.aid);
        int4 mpNN = __ldg((const int4*)item_meta + idNN.pid);
        int4 mnNN = __ldg((const int4*)item_meta + idNN.nid);

        // ================= compute phase 2 =================
        // rbar = sum_r rel[r]*rue[r]  (||rue||^2 term cancels in pos-neg diff)
        const float GAMMA = 0.5f;
        float2 rbar;
        rbar.x = GAMMA * (rw[0] * re[0].x + rw[1] * re[1].x + rw[2] * re[2].x) + (1.f - GAMMA) * eC.u.x;
        rbar.y = GAMMA * (rw[0] * re[0].y + rw[1] * re[1].y + rw[2] * re[2].y) + (1.f - GAMMA) * eC.u.y;

        // seq score difference in one reduction
        float diffpn;
        {
            float sdp = 0.f, dbxp = 0.f, dbyp = 0.f;
            float sdn = 0.f, dbxn = 0.f, dbyn = 0.f;
            float dx = eC.a.x - eC.p.x, dy = eC.a.y - eC.p.y;
            sdp += cf[0] * (dx * dx + dy * dy); dbxp += cf[0] * dx; dbyp += cf[0] * dy;
            dx = eC.a.x - eC.n.x; dy = eC.a.y - eC.n.y;
            sdn += cf[0] * (dx * dx + dy * dy); dbxn += cf[0] * dx; dbyn += cf[0] * dy;
#pragma unroll
            for (int g = 0; g < 4; g++) {
                dx = eC.am[g].x - eC.pm[g].x; dy = eC.am[g].y - eC.pm[g].y;
                sdp += cf[1 + g] * (dx * dx + dy * dy);
                dbxp += cf[1 + g] * dx; dbyp += cf[1 + g] * dy;
                dx = eC.am[g].x - eC.nm[g].x; dy = eC.am[g].y - eC.nm[g].y;
                sdn += cf[1 + g] * (dx * dx + dy * dy);
                dbxn += cf[1 + g] * dx; dbyn += cf[1 + g] * dy;
            }
            float sp = sdp + 2.f * (dbxp * rbar.x + dbyp * rbar.y);
            float sn = sdn + 2.f * (dbxn * rbar.x + dbyn * rbar.y);
            diffpn = wsum(sp - sn);
        }

        // item loss pieces
        float2 iir;
        iir.x = (idC.prid == 0) ? re[0].x : ((idC.prid == 1) ? re[1].x : re[2].x);
        iir.y = (idC.prid == 0) ? re[0].y : ((idC.prid == 1) ? re[1].y : re[2].y);
        float px = eC.a.x + iir.x - eC.p.x,   py = eC.a.y + iir.y - eC.p.y;
        float qx = eC.a.x + iir.x - eC.nri.x, qy = eC.a.y + iir.y - eC.nri.y;
        float di = wsum((px * px + py * py) - (qx * qx + qy * qy));

        // accumulate (this sample is guaranteed valid: loop condition b < B)
        accSeq += nlsig((eC.biasP - eC.biasN) - diffpn);
        float prs = (idC.prid == 0) ? rw[0] : ((idC.prid == 1) ? rw[1] : rw[2]);
        float nrs = (idC.nrel == 0) ? rw[0] : ((idC.nrel == 1) ? rw[1] : rw[2]);
        accRel += nlsig(prs - nrs);
        accItm += nlsig((eC.biasP - eC.biasNR) - di);

        // ---- rotate pipeline
        idC = idN; idN = idNN;
        maN = maNN; mpN = mpNN; mnN = mnNN;
        eC = eN;
    }

    // ---- deterministic block-level partial sum
    __shared__ float sh[WARPS_PER_BLOCK][3];
    __shared__ bool is_last;
    if (lane == 0) { sh[wid][0] = accSeq; sh[wid][1] = accRel; sh[wid][2] = accItm; }
    __syncthreads();
    if (threadIdx.x == 0) {
        float s0 = 0.f, s1 = 0.f, s2 = 0.f;
#pragma unroll
        for (int w = 0; w < WARPS_PER_BLOCK; w++) {
            s0 += sh[w][0]; s1 += sh[w][1]; s2 += sh[w][2];
        }
        g_partials[blockIdx.x * 3 + 0] = s0;
        g_partials[blockIdx.x * 3 + 1] = s1;
        g_partials[blockIdx.x * 3 + 2] = s2;
        __threadfence();
        unsigned int old = atomicAdd(&g_count, 1u);
        is_last = (old == gridDim.x - 1);
    }
    __syncthreads();

    // ---- last arriving block does the final (fixed-order, deterministic) reduce
    if (is_last) {
        const int nblocks = gridDim.x;
        __shared__ float shf[3];
        if (wid < 3) {
            float s = 0.f;
            for (int i = lane; i < nblocks; i += 32) s += g_partials[i * 3 + wid];
            s = wsum(s) * invB;
            if (lane == 0) shf[wid] = s;
        }
        __syncthreads();
        if (threadIdx.x == 0) {
            float seq = shf[0], rel = shf[1], itm = shf[2];
            out[0] = seq + rel + itm;   // loss (ALPHA=BETA=1)
            out[1] = rel;               // relation_loss
            out[2] = seq;               // seq_loss
            out[3] = itm;               // item_loss
            g_count = 0;                // reset for next graph replay
        }
    }
}

extern "C" void kernel_launch(void* const* d_in, const int* in_sizes, int n_in,
                              void* d_out, int out_size) {
    const int*   u_id       = (const int*)d_in[0];
    const int*   anchor_i   = (const int*)d_in[1];
    const int*   pos_r      = (const int*)d_in[2];
    const int*   pos_i      = (const int*)d_in[3];
    const int*   neg_r      = (const int*)d_in[4];
    const int*   neg_i      = (const int*)d_in[5];
    const int*   neg_ri     = (const int*)d_in[6];
    const int*   item_meta  = (const int*)d_in[7];
    const float* user_emb   = (const float*)d_in[8];
    const float* rel_emb    = (const float*)d_in[9];
    const float* item_emb   = (const float*)d_in[10];
    const float* item_emb_r = (const float*)d_in[11];
    const float* item_bias  = (const float*)d_in[12];
    const float* rel_bias   = (const float*)d_in[13];
    const float* meta_emb   = (const float*)d_in[14];
    const float* att_w_W    = (const float*)d_in[15];
    const float* att_v_W    = (const float*)d_in[17];

    const int B = in_sizes[0];

    precompute_w2<<<1, 64>>>(att_w_W, att_v_W);
    actr_main<<<GRID_BLOCKS, THREADS>>>(u_id, anchor_i, pos_r, pos_i, neg_r, neg_i, neg_ri,
                                        item_meta, user_emb, rel_emb, item_emb, item_emb_r,
                                        item_bias, rel_bias, meta_emb,
                                        (float*)d_out, B, 1.0f / (float)B);
}